// round 2
// baseline (speedup 1.0000x reference)
#include <cuda_runtime.h>
#include <math.h>

#define BNUM 1024
#define TT   48
#define NT   47
#define RNNV 64
#define GG   256
#define NOBJ 25
#define HID  32
#define V1   2001
#define NROW (NT*BNUM)

__device__ float g_xproj[(size_t)NROW*GG];
__device__ float g_hist[(size_t)NROW*RNNV];
__device__ float g_pre1[BNUM*NOBJ*HID];
__device__ float g_pre2[BNUM*NOBJ*HID];
__device__ float g_diff[BNUM*NOBJ*4];
__device__ float g_WAl[RNNV*GG], g_WAh[RNNV*GG], g_WAx[RNNV*GG];
__device__ float g_WLa[RNNV*GG], g_WLh[RNNV*GG], g_WLl[RNNV*GG];
__device__ float g_fcwT[RNNV*V1];

typedef unsigned long long u64;

__device__ __forceinline__ u64 pack2(float lo, float hi){
    u64 r; asm("mov.b64 %0, {%1, %2};" : "=l"(r) : "f"(lo), "f"(hi)); return r;
}
__device__ __forceinline__ u64 dup2(float x){ return pack2(x, x); }
__device__ __forceinline__ void fma2(u64& acc, u64 a, u64 b){
    asm("fma.rn.f32x2 %0, %1, %2, %0;" : "+l"(acc) : "l"(a), "l"(b));
}
__device__ __forceinline__ float2 unpack2(u64 v){
    float2 f; asm("mov.b64 {%0, %1}, %2;" : "=f"(f.x), "=f"(f.y) : "l"(v)); return f;
}
__device__ __forceinline__ float sigf(float x){ return 1.0f/(1.0f + __expf(-x)); }

// ------------------------------------------------------------------
__global__ void prep_weights_kernel(const float* __restrict__ WihA, const float* __restrict__ WhhA,
                                    const float* __restrict__ WihL, const float* __restrict__ WhhL,
                                    const float* __restrict__ fcw)
{
    int i = blockIdx.x*blockDim.x + threadIdx.x;
    if (i < RNNV*GG){
        int k = i / GG, g = i % GG;
        g_WAl[i] = WihA[g*128 + k];
        g_WAx[i] = WihA[g*128 + 64 + k];
        g_WAh[i] = WhhA[g*64 + k];
        g_WLa[i] = WihL[g*128 + k];
        g_WLh[i] = WihL[g*128 + 64 + k];
        g_WLl[i] = WhhL[g*64 + k];
    }
    if (i < RNNV*V1){
        int k = i / V1, v = i % V1;
        g_fcwT[i] = fcw[v*RNNV + k];
    }
}

// ------------------------------------------------------------------
__global__ void prep_canvas_kernel(const float* __restrict__ prev, const float* __restrict__ finalc,
                                   const float* __restrict__ a1w1, const float* __restrict__ a1b1,
                                   const float* __restrict__ a2w1, const float* __restrict__ a2b1)
{
    int i = blockIdx.x*blockDim.x + threadIdx.x;
    if (i >= BNUM*NOBJ*HID) return;
    int j = i & 31, bn = i >> 5;
    float p0 = prev[bn*4+0], p1 = prev[bn*4+1], p2 = prev[bn*4+2], p3 = prev[bn*4+3];
    bool masked = (p0+p1+p2+p3) > 0.0f;
    float d0 = masked ? -1.0f : finalc[bn*4+0];
    float d1 = masked ? -1.0f : finalc[bn*4+1];
    float d2 = masked ? -1.0f : finalc[bn*4+2];
    float d3 = masked ? -1.0f : finalc[bn*4+3];
    const float* w1 = a1w1 + j*68 + 64;
    const float* w2 = a2w1 + j*68 + 64;
    g_pre1[i] = a1b1[j] + d0*w1[0] + d1*w1[1] + d2*w1[2] + d3*w1[3];
    g_pre2[i] = a2b1[j] + p0*w2[0] + p1*w2[1] + p2*w2[2] + p3*w2[3];
    if (j == 0){
        g_diff[bn*4+0] = d0; g_diff[bn*4+1] = d1;
        g_diff[bn*4+2] = d2; g_diff[bn*4+3] = d3;
    }
}

// ------------------------------------------------------------------
// xproj[m][g] = b_ih[g] + b_hh[g] + sum_k embed[inst][k] * W_ih_att[g][64+k]
__global__ __launch_bounds__(256) void xproj_kernel(
    const int* __restrict__ inst, const float* __restrict__ embed,
    const float* __restrict__ b_ih, const float* __restrict__ b_hh)
{
    __shared__ __align__(16) float se[RNNV*16];  // [k][r]
    const int tid = threadIdx.x;
    const int m0 = blockIdx.x * 16;
    for (int i = tid; i < 16*RNNV; i += 256){
        int r = i >> 6, k = i & 63;
        int m = m0 + r;
        int t = m >> 10, b = m & 1023;
        int tok = inst[b*TT + t];
        se[k*16 + r] = embed[tok*RNNV + k];
    }
    __syncthreads();
    const int g = tid;
    float bias = b_ih[g] + b_hh[g];
    u64 acc[8];
    #pragma unroll
    for (int p = 0; p < 8; ++p) acc[p] = dup2(bias);
    const float* w = g_WAx + g;
    #pragma unroll 8
    for (int k = 0; k < RNNV; ++k){
        u64 wd = dup2(w[k*GG]);
        const u64* e = (const u64*)(se + k*16);
        #pragma unroll
        for (int p = 0; p < 8; ++p) fma2(acc[p], wd, e[p]);
    }
    float* xp = g_xproj + (size_t)m0*GG + g;
    #pragma unroll
    for (int p = 0; p < 8; ++p){
        float2 f = unpack2(acc[p]);
        xp[(size_t)(2*p)*GG]   = f.x;
        xp[(size_t)(2*p+1)*GG] = f.y;
    }
}

// ------------------------------------------------------------------
// persistent recurrence: 128 CTAs x 8 batch rows, 47 steps
__global__ __launch_bounds__(256) void recurrent_kernel(
    const float* __restrict__ a1w1, const float* __restrict__ a1w2, const float* __restrict__ a1b2,
    const float* __restrict__ a2w1, const float* __restrict__ a2w2, const float* __restrict__ a2b2,
    const float* __restrict__ tw1,  const float* __restrict__ tb1,
    const float* __restrict__ tw2,  const float* __restrict__ tb2,
    const float* __restrict__ bihl, const float* __restrict__ bhhl,
    const float* __restrict__ prev)
{
    __shared__ __align__(16) float s_hl[RNNV*10];
    __shared__ __align__(16) float s_ha[RNNV*10];
    __shared__ __align__(16) float s_av[RNNV*10];
    __shared__ float s_ca[8*RNNV], s_cl[8*RNNV];
    __shared__ float s_g[8*GG];
    __shared__ float s_mem[2][8][NOBJ*4];
    __shared__ float s_hp[8*2*HID];
    __shared__ float s_s[8*2*NOBJ];
    __shared__ float s_ao[8][8];
    __shared__ float s_t1[8*HID];
    __shared__ float s_tw1t[8*HID];   // [d][j]
    __shared__ float s_w2a[2][HID];
    __shared__ float s_tb1[HID], s_tb2[RNNV];
    __shared__ float s_blang[GG];
    __shared__ float s_b2a[2];

    const int tid  = threadIdx.x;
    const int row0 = blockIdx.x * 8;

    for (int i = tid; i < RNNV*10; i += 256){ s_hl[i]=0.f; s_ha[i]=0.f; s_av[i]=0.f; }
    for (int i = tid; i < 8*RNNV; i += 256){ s_cl[i]=0.f; s_ca[i]=0.f; }
    for (int i = tid; i < 8*NOBJ*4; i += 256){
        int r = i/100, rem = i%100;
        s_mem[0][r][rem] = g_diff[(row0+r)*100 + rem];
        s_mem[1][r][rem] = prev[(row0+r)*100 + rem];
    }
    { int j = tid >> 3, d = tid & 7; s_tw1t[d*HID + j] = tw1[j*8 + d]; }
    if (tid < HID){ s_w2a[0][tid] = a1w2[tid]; s_w2a[1][tid] = a2w2[tid]; s_tb1[tid] = tb1[tid]; }
    if (tid < RNNV) s_tb2[tid] = tb2[tid];
    s_blang[tid] = bihl[tid] + bhhl[tid];
    if (tid < 2) s_b2a[tid] = tid ? a2b2[0] : a1b2[0];
    __syncthreads();

    for (int t = 0; t < NT; ++t){
        // attention-LSTM gates
        {
            const int g = tid;
            const float* xp = g_xproj + ((size_t)t*BNUM + row0)*GG + g;
            u64 acc0 = pack2(xp[0*GG], xp[1*GG]);
            u64 acc1 = pack2(xp[2*GG], xp[3*GG]);
            u64 acc2 = pack2(xp[4*GG], xp[5*GG]);
            u64 acc3 = pack2(xp[6*GG], xp[7*GG]);
            const float* wl = g_WAl + g;
            const float* wh = g_WAh + g;
            #pragma unroll 8
            for (int k = 0; k < RNNV; ++k){
                u64 w0 = dup2(wl[k*GG]);
                u64 w1 = dup2(wh[k*GG]);
                const u64* hl = (const u64*)(s_hl + k*10);
                const u64* ha = (const u64*)(s_ha + k*10);
                fma2(acc0, w0, hl[0]); fma2(acc0, w1, ha[0]);
                fma2(acc1, w0, hl[1]); fma2(acc1, w1, ha[1]);
                fma2(acc2, w0, hl[2]); fma2(acc2, w1, ha[2]);
                fma2(acc3, w0, hl[3]); fma2(acc3, w1, ha[3]);
            }
            float2 f;
            f = unpack2(acc0); s_g[0*GG+g]=f.x; s_g[1*GG+g]=f.y;
            f = unpack2(acc1); s_g[2*GG+g]=f.x; s_g[3*GG+g]=f.y;
            f = unpack2(acc2); s_g[4*GG+g]=f.x; s_g[5*GG+g]=f.y;
            f = unpack2(acc3); s_g[6*GG+g]=f.x; s_g[7*GG+g]=f.y;
        }
        __syncthreads();
        // attention LSTM cell
        #pragma unroll
        for (int ii = 0; ii < 2; ++ii){
            int i = tid + ii*256;
            int u = i & 63, r = i >> 6;
            float gi = s_g[r*GG + u], gf = s_g[r*GG + 64 + u];
            float gg = s_g[r*GG + 128 + u], go = s_g[r*GG + 192 + u];
            float c = sigf(gf) * s_ca[r*RNNV+u] + sigf(gi) * tanhf(gg);
            s_ca[r*RNNV+u] = c;
            s_ha[u*10 + r] = sigf(go) * tanhf(c);
        }
        __syncthreads();
        // attention h-projection  hp[r][a][j] = h_att . w1[j][:64]
        #pragma unroll
        for (int ii = 0; ii < 2; ++ii){
            int i = tid + ii*256;
            int r = i >> 6, a = (i >> 5) & 1, j = i & 31;
            const float4* w = (const float4*)((a ? a2w1 : a1w1) + j*68);
            float acc = 0.0f;
            #pragma unroll
            for (int kq = 0; kq < 16; ++kq){
                float4 wv = __ldg(w + kq);
                int k = kq*4;
                acc += wv.x*s_ha[(k+0)*10+r] + wv.y*s_ha[(k+1)*10+r]
                     + wv.z*s_ha[(k+2)*10+r] + wv.w*s_ha[(k+3)*10+r];
            }
            s_hp[(r*2+a)*HID + j] = acc;
        }
        __syncthreads();
        // scores
        #pragma unroll
        for (int ii = 0; ii < 2; ++ii){
            int i = tid + ii*256;
            if (i < 400){
                int r = i / 50, rem = i % 50;
                int a = rem / 25, n = rem % 25;
                const float4* pre = (const float4*)((a ? g_pre2 : g_pre1) + ((size_t)(row0+r)*NOBJ + n)*HID);
                const float* hp = s_hp + (r*2+a)*HID;
                const float* w2 = s_w2a[a];
                float acc = s_b2a[a];
                #pragma unroll
                for (int jq = 0; jq < 8; ++jq){
                    float4 pv = __ldg(pre + jq);
                    int j = jq*4;
                    acc += fmaxf(hp[j+0]+pv.x, 0.f) * w2[j+0];
                    acc += fmaxf(hp[j+1]+pv.y, 0.f) * w2[j+1];
                    acc += fmaxf(hp[j+2]+pv.z, 0.f) * w2[j+2];
                    acc += fmaxf(hp[j+3]+pv.w, 0.f) * w2[j+3];
                }
                s_s[(r*2+a)*NOBJ + n] = acc;
            }
        }
        __syncthreads();
        // softmax over objects + weighted memory sum
        if (tid < 16){
            int r = tid >> 1, a = tid & 1;
            const float* sv = s_s + (r*2+a)*NOBJ;
            float m = sv[0];
            #pragma unroll
            for (int n = 1; n < NOBJ; ++n) m = fmaxf(m, sv[n]);
            float sum=0.f, o0=0.f, o1=0.f, o2=0.f, o3=0.f;
            const float* mem = s_mem[a][r];
            #pragma unroll
            for (int n = 0; n < NOBJ; ++n){
                float e = __expf(sv[n]-m);
                sum += e;
                o0 += e*mem[n*4+0]; o1 += e*mem[n*4+1];
                o2 += e*mem[n*4+2]; o3 += e*mem[n*4+3];
            }
            float inv = 1.0f/sum;
            s_ao[r][a*4+0]=o0*inv; s_ao[r][a*4+1]=o1*inv;
            s_ao[r][a*4+2]=o2*inv; s_ao[r][a*4+3]=o3*inv;
        }
        __syncthreads();
        // trans layer 1
        {
            int r = tid >> 5, j = tid & 31;
            float acc = s_tb1[j];
            #pragma unroll
            for (int d = 0; d < 8; ++d) acc += s_ao[r][d] * s_tw1t[d*HID + j];
            s_t1[r*HID + j] = fmaxf(acc, 0.0f);
        }
        __syncthreads();
        // trans layer 2
        #pragma unroll
        for (int ii = 0; ii < 2; ++ii){
            int i = tid + ii*256;
            int u = i & 63, r = i >> 6;
            const float4* w = (const float4*)(tw2 + u*HID);
            const float* t1 = s_t1 + r*HID;
            float acc = s_tb2[u];
            #pragma unroll
            for (int jq = 0; jq < 8; ++jq){
                float4 wv = __ldg(w + jq);
                int j = jq*4;
                acc += wv.x*t1[j] + wv.y*t1[j+1] + wv.z*t1[j+2] + wv.w*t1[j+3];
            }
            s_av[u*10 + r] = acc;
        }
        __syncthreads();
        // language-LSTM gates
        {
            const int g = tid;
            u64 acc0 = dup2(s_blang[g]), acc1 = acc0, acc2 = acc0, acc3 = acc0;
            const float* wa = g_WLa + g;
            const float* wh = g_WLh + g;
            const float* wl = g_WLl + g;
            #pragma unroll 8
            for (int k = 0; k < RNNV; ++k){
                u64 w0 = dup2(wa[k*GG]);
                u64 w1 = dup2(wh[k*GG]);
                u64 w2 = dup2(wl[k*GG]);
                const u64* av = (const u64*)(s_av + k*10);
                const u64* ha = (const u64*)(s_ha + k*10);
                const u64* hl = (const u64*)(s_hl + k*10);
                fma2(acc0, w0, av[0]); fma2(acc0, w1, ha[0]); fma2(acc0, w2, hl[0]);
                fma2(acc1, w0, av[1]); fma2(acc1, w1, ha[1]); fma2(acc1, w2, hl[1]);
                fma2(acc2, w0, av[2]); fma2(acc2, w1, ha[2]); fma2(acc2, w2, hl[2]);
                fma2(acc3, w0, av[3]); fma2(acc3, w1, ha[3]); fma2(acc3, w2, hl[3]);
            }
            float2 f;
            f = unpack2(acc0); s_g[0*GG+g]=f.x; s_g[1*GG+g]=f.y;
            f = unpack2(acc1); s_g[2*GG+g]=f.x; s_g[3*GG+g]=f.y;
            f = unpack2(acc2); s_g[4*GG+g]=f.x; s_g[5*GG+g]=f.y;
            f = unpack2(acc3); s_g[6*GG+g]=f.x; s_g[7*GG+g]=f.y;
        }
        __syncthreads();
        // language LSTM cell + history write
        #pragma unroll
        for (int ii = 0; ii < 2; ++ii){
            int i = tid + ii*256;
            int u = i & 63, r = i >> 6;
            float gi = s_g[r*GG + u], gf = s_g[r*GG + 64 + u];
            float gg = s_g[r*GG + 128 + u], go = s_g[r*GG + 192 + u];
            float c = sigf(gf) * s_cl[r*RNNV+u] + sigf(gi) * tanhf(gg);
            s_cl[r*RNNV+u] = c;
            float h = sigf(go) * tanhf(c);
            s_hl[u*10 + r] = h;
            g_hist[((size_t)t*BNUM + row0 + r)*RNNV + u] = h;
        }
        __syncthreads();
    }
}

// ------------------------------------------------------------------
// fused output GEMM + log_softmax: CTA = 16 rows x 2001 cols, logits in smem
#define LST 18   // smem logit col stride (16 rows + 2 pad), 2-way-conflict banks
__global__ __launch_bounds__(256) void output_kernel(const float* __restrict__ fcb,
                                                     float* __restrict__ out)
{
    extern __shared__ __align__(16) float s_logit[];     // [V1][LST]
    __shared__ __align__(16) float s_h[RNNV*16];          // [k][r]
    __shared__ float s_lse[16];
    const int tid = threadIdx.x;
    const int m0  = blockIdx.x * 16;

    // stage h history (transpose to [k][r])
    {
        int r = tid >> 4, k4 = (tid & 15) * 4;
        const float4 v = *(const float4*)(g_hist + (size_t)(m0 + r)*RNNV + k4);
        s_h[(k4+0)*16 + r] = v.x; s_h[(k4+1)*16 + r] = v.y;
        s_h[(k4+2)*16 + r] = v.z; s_h[(k4+3)*16 + r] = v.w;
    }
    __syncthreads();

    #pragma unroll
    for (int chunk = 0; chunk < 8; ++chunk){
        int c  = chunk*256 + tid;
        int cc = c < V1 ? c : V1-1;
        u64 acc[8];
        float bias = fcb[cc];
        #pragma unroll
        for (int p = 0; p < 8; ++p) acc[p] = dup2(bias);
        const float* w = g_fcwT + cc;
        #pragma unroll 16
        for (int k = 0; k < RNNV; ++k){
            u64 wd = dup2(w[(size_t)k*V1]);
            const u64* hp = (const u64*)(s_h + k*16);
            #pragma unroll
            for (int p = 0; p < 8; ++p) fma2(acc[p], wd, hp[p]);
        }
        if (c < V1){
            #pragma unroll
            for (int p = 0; p < 8; ++p)
                *(u64*)(s_logit + c*LST + 2*p) = acc[p];
        }
    }
    __syncthreads();

    // per-row logsumexp (logits are small; skip max-shift)
    {
        int r = tid >> 4, sub = tid & 15;
        float part = 0.0f;
        for (int c = sub; c < V1; c += 16)
            part += __expf(s_logit[c*LST + r]);
        #pragma unroll
        for (int o = 8; o; o >>= 1)
            part += __shfl_xor_sync(0xffffffffu, part, o);
        if (sub == 0) s_lse[r] = __logf(part);
    }
    __syncthreads();

    // write normalized log-probs: out[b][t][v]
    for (int r = 0; r < 16; ++r){
        int m = m0 + r;
        int t = m >> 10, b = m & 1023;
        float lse = s_lse[r];
        float* dst = out + ((size_t)b*NT + t)*V1;
        for (int c = tid; c < V1; c += 256)
            dst[c] = s_logit[c*LST + r] - lse;
    }
}

// ------------------------------------------------------------------
extern "C" void kernel_launch(void* const* d_in, const int* in_sizes, int n_in,
                              void* d_out, int out_size)
{
    const int*   inst  = (const int*)  d_in[0];
    const float* prevc = (const float*)d_in[1];
    const float* finc  = (const float*)d_in[2];
    const float* embed = (const float*)d_in[3];
    const float* WihA  = (const float*)d_in[4];
    const float* WhhA  = (const float*)d_in[5];
    const float* bihA  = (const float*)d_in[6];
    const float* bhhA  = (const float*)d_in[7];
    const float* WihL  = (const float*)d_in[8];
    const float* WhhL  = (const float*)d_in[9];
    const float* bihL  = (const float*)d_in[10];
    const float* bhhL  = (const float*)d_in[11];
    const float* fcw   = (const float*)d_in[12];
    const float* fcb   = (const float*)d_in[13];
    const float* a1w1  = (const float*)d_in[14];
    const float* a1b1  = (const float*)d_in[15];
    const float* a1w2  = (const float*)d_in[16];
    const float* a1b2  = (const float*)d_in[17];
    const float* a2w1  = (const float*)d_in[18];
    const float* a2b1  = (const float*)d_in[19];
    const float* a2w2  = (const float*)d_in[20];
    const float* a2b2  = (const float*)d_in[21];
    const float* tw1   = (const float*)d_in[22];
    const float* tb1   = (const float*)d_in[23];
    const float* tw2   = (const float*)d_in[24];
    const float* tb2   = (const float*)d_in[25];
    float* out = (float*)d_out;

    static int smem_set = 0;
    const int logit_smem = V1 * LST * (int)sizeof(float);
    if (!smem_set){
        cudaFuncSetAttribute(output_kernel, cudaFuncAttributeMaxDynamicSharedMemorySize, logit_smem);
        smem_set = 1;
    }

    prep_weights_kernel<<<(RNNV*V1 + 255)/256, 256>>>(WihA, WhhA, WihL, WhhL, fcw);
    prep_canvas_kernel<<<(BNUM*NOBJ*HID + 255)/256, 256>>>(prevc, finc, a1w1, a1b1, a2w1, a2b1);
    xproj_kernel<<<NROW/16, 256>>>(inst, embed, bihA, bhhA);
    recurrent_kernel<<<BNUM/8, 256>>>(a1w1, a1w2, a1b2, a2w1, a2w2, a2b2,
                                      tw1, tb1, tw2, tb2, bihL, bhhL, prevc);
    output_kernel<<<NROW/16, 256, logit_smem>>>(fcb, out);
}

// round 3
// speedup vs baseline: 1.2876x; 1.2876x over previous
#include <cuda_runtime.h>
#include <math.h>

#define BNUM 1024
#define TT   48
#define NT   47
#define RNNV 64
#define GG   256
#define NOBJ 25
#define HID  32
#define V1   2001
#define NROW (NT*BNUM)

__device__ float g_xproj[(size_t)NROW*GG];
__device__ float g_hist[(size_t)NROW*RNNV];
__device__ float g_pre1[BNUM*NOBJ*HID];
__device__ float g_pre2[BNUM*NOBJ*HID];
__device__ float g_diff[BNUM*NOBJ*4];
__device__ float g_WAl[RNNV*GG], g_WAh[RNNV*GG], g_WAx[RNNV*GG];
__device__ float g_WLa[RNNV*GG], g_WLh[RNNV*GG], g_WLl[RNNV*GG];
__device__ float g_fcwT[RNNV*V1];

typedef unsigned long long u64;

__device__ __forceinline__ u64 pack2(float lo, float hi){
    u64 r; asm("mov.b64 %0, {%1, %2};" : "=l"(r) : "f"(lo), "f"(hi)); return r;
}
__device__ __forceinline__ u64 dup2(float x){ return pack2(x, x); }
__device__ __forceinline__ void fma2(u64& acc, u64 a, u64 b){
    asm("fma.rn.f32x2 %0, %1, %2, %0;" : "+l"(acc) : "l"(a), "l"(b));
}
__device__ __forceinline__ float2 unpack2(u64 v){
    float2 f; asm("mov.b64 {%0, %1}, %2;" : "=f"(f.x), "=f"(f.y) : "l"(v)); return f;
}
__device__ __forceinline__ float sigf(float x){ return 1.0f/(1.0f + __expf(-x)); }

// ------------------------------------------------------------------
__global__ void prep_weights_kernel(const float* __restrict__ WihA, const float* __restrict__ WhhA,
                                    const float* __restrict__ WihL, const float* __restrict__ WhhL,
                                    const float* __restrict__ fcw)
{
    int i = blockIdx.x*blockDim.x + threadIdx.x;
    if (i < RNNV*GG){
        int k = i / GG, g = i % GG;
        g_WAl[i] = WihA[g*128 + k];
        g_WAx[i] = WihA[g*128 + 64 + k];
        g_WAh[i] = WhhA[g*64 + k];
        g_WLa[i] = WihL[g*128 + k];
        g_WLh[i] = WihL[g*128 + 64 + k];
        g_WLl[i] = WhhL[g*64 + k];
    }
    if (i < RNNV*V1){
        int k = i / V1, v = i % V1;
        g_fcwT[i] = fcw[v*RNNV + k];
    }
}

// ------------------------------------------------------------------
__global__ void prep_canvas_kernel(const float* __restrict__ prev, const float* __restrict__ finalc,
                                   const float* __restrict__ a1w1, const float* __restrict__ a1b1,
                                   const float* __restrict__ a2w1, const float* __restrict__ a2b1)
{
    int i = blockIdx.x*blockDim.x + threadIdx.x;
    if (i >= BNUM*NOBJ*HID) return;
    int j = i & 31, bn = i >> 5;
    float p0 = prev[bn*4+0], p1 = prev[bn*4+1], p2 = prev[bn*4+2], p3 = prev[bn*4+3];
    bool masked = (p0+p1+p2+p3) > 0.0f;
    float d0 = masked ? -1.0f : finalc[bn*4+0];
    float d1 = masked ? -1.0f : finalc[bn*4+1];
    float d2 = masked ? -1.0f : finalc[bn*4+2];
    float d3 = masked ? -1.0f : finalc[bn*4+3];
    const float* w1 = a1w1 + j*68 + 64;
    const float* w2 = a2w1 + j*68 + 64;
    g_pre1[i] = a1b1[j] + d0*w1[0] + d1*w1[1] + d2*w1[2] + d3*w1[3];
    g_pre2[i] = a2b1[j] + p0*w2[0] + p1*w2[1] + p2*w2[2] + p3*w2[3];
    if (j == 0){
        g_diff[bn*4+0] = d0; g_diff[bn*4+1] = d1;
        g_diff[bn*4+2] = d2; g_diff[bn*4+3] = d3;
    }
}

// ------------------------------------------------------------------
__global__ __launch_bounds__(256) void xproj_kernel(
    const int* __restrict__ inst, const float* __restrict__ embed,
    const float* __restrict__ b_ih, const float* __restrict__ b_hh)
{
    __shared__ __align__(16) float se[RNNV*16];  // [k][r]
    const int tid = threadIdx.x;
    const int m0 = blockIdx.x * 16;
    for (int i = tid; i < 16*RNNV; i += 256){
        int r = i >> 6, k = i & 63;
        int m = m0 + r;
        int t = m >> 10, b = m & 1023;
        int tok = inst[b*TT + t];
        se[k*16 + r] = embed[tok*RNNV + k];
    }
    __syncthreads();
    const int g = tid;
    float bias = b_ih[g] + b_hh[g];
    u64 acc[8];
    #pragma unroll
    for (int p = 0; p < 8; ++p) acc[p] = dup2(bias);
    const float* w = g_WAx + g;
    #pragma unroll 8
    for (int k = 0; k < RNNV; ++k){
        u64 wd = dup2(w[k*GG]);
        const float* e = se + k*16;
        ulonglong2 e0 = *(const ulonglong2*)(e);
        ulonglong2 e1 = *(const ulonglong2*)(e + 4);
        ulonglong2 e2 = *(const ulonglong2*)(e + 8);
        ulonglong2 e3 = *(const ulonglong2*)(e + 12);
        fma2(acc[0], wd, e0.x); fma2(acc[1], wd, e0.y);
        fma2(acc[2], wd, e1.x); fma2(acc[3], wd, e1.y);
        fma2(acc[4], wd, e2.x); fma2(acc[5], wd, e2.y);
        fma2(acc[6], wd, e3.x); fma2(acc[7], wd, e3.y);
    }
    float* xp = g_xproj + (size_t)m0*GG + g;
    #pragma unroll
    for (int p = 0; p < 8; ++p){
        float2 f = unpack2(acc[p]);
        xp[(size_t)(2*p)*GG]   = f.x;
        xp[(size_t)(2*p+1)*GG] = f.y;
    }
}

// ------------------------------------------------------------------
// shared memory layout (floats) for recurrent kernel
#define R_HL    0        // 512   h_lang [k][r] stride 8
#define R_HA    512      // 512   h_att
#define R_AV    1024     // 512   trans output
#define R_CA    1536     // 512   c_att [r][u]
#define R_CL    2048     // 512   c_lang
#define R_PART  2560     // 4096  gate partials [half][r][g]
#define R_PRE   6656     // 12800 pre [(a*32+j)*8+r]*25+n
#define R_W1H   19456    // 4096  w1 head part [(a*64+k)*32+j]
#define R_TW2T  23552    // 2048  trans_w2 T [j][u]
#define R_MEM   25600    // 1600  [a][r][n*4+d]
#define R_HP    27200    // 512
#define R_SS    27712    // 400
#define R_AO    28112    // 64
#define R_T1    28176    // 256
#define R_TW1T  28432    // 256  [d][j]
#define R_W2A   28688    // 64   [a][j]
#define R_TB1   28752    // 32
#define R_TB2   28784    // 64
#define R_BL    28848    // 256
#define R_B2A   29104    // 2
#define R_TOTAL 29108

__global__ __launch_bounds__(512) void recurrent_kernel(
    const float* __restrict__ a1w1, const float* __restrict__ a1w2, const float* __restrict__ a1b2,
    const float* __restrict__ a2w1, const float* __restrict__ a2w2, const float* __restrict__ a2b2,
    const float* __restrict__ tw1,  const float* __restrict__ tb1,
    const float* __restrict__ tw2,  const float* __restrict__ tb2,
    const float* __restrict__ bihl, const float* __restrict__ bhhl,
    const float* __restrict__ prev)
{
    extern __shared__ __align__(16) float sm[];
    const int tid  = threadIdx.x;
    const int row0 = blockIdx.x * 8;

    // ------- one-time init -------
    for (int i = tid; i < 2560; i += 512) sm[i] = 0.f;  // HL, HA, AV, CA, CL
    for (int i = tid; i < 12800; i += 512){
        int j = i & 31, n = (i >> 5) % 25, r = (i / 800) & 7, a = i / 6400;
        const float* src = a ? g_pre2 : g_pre1;
        sm[R_PRE + a*6400 + j*200 + r*25 + n] = src[((size_t)(row0+r)*NOBJ + n)*HID + j];
    }
    for (int i = tid; i < 4096; i += 512){
        int k = i & 63, j = (i >> 6) & 31, a = i >> 11;
        sm[R_W1H + (a*64 + k)*32 + j] = (a ? a2w1 : a1w1)[j*68 + k];
    }
    for (int i = tid; i < 2048; i += 512){
        int u = i & 63, j = i >> 6;
        sm[R_TW2T + j*64 + u] = tw2[u*HID + j];
    }
    for (int i = tid; i < 1600; i += 512){
        int a = i / 800, rem = i % 800, r = rem / 100, q = rem % 100;
        sm[R_MEM + i] = a ? prev[(row0+r)*100 + q] : g_diff[(row0+r)*100 + q];
    }
    if (tid < 256){ int j = tid >> 3, d = tid & 7; sm[R_TW1T + d*32 + j] = tw1[j*8 + d]; }
    if (tid < 32){
        sm[R_W2A + tid]      = a1w2[tid];
        sm[R_W2A + 32 + tid] = a2w2[tid];
        sm[R_TB1 + tid]      = tb1[tid];
    }
    if (tid < 64)  sm[R_TB2 + tid] = tb2[tid];
    if (tid < 256) sm[R_BL + tid]  = bihl[tid] + bhhl[tid];
    if (tid < 2)   sm[R_B2A + tid] = tid ? a2b2[0] : a1b2[0];
    __syncthreads();

    // ------- hoisted per-thread indices -------
    const int g   = tid & 255;
    const int hf  = tid >> 8;
    const int k0  = hf << 5;
    const int cu  = tid & 63, cr = tid >> 6;                       // cell / trans2
    const int hr  = tid >> 6, hav = (tid >> 5) & 1, hj = tid & 31; // hp
    const int sr  = tid / 50, srem = tid % 50;                     // scores
    const int sa  = srem / 25, sn = srem % 25;
    const int t1r = tid >> 5, t1j = tid & 31;                      // trans1

    const float* wAl = g_WAl + (size_t)k0*GG + g;
    const float* wAh = g_WAh + (size_t)k0*GG + g;
    const float* wLa = g_WLa + (size_t)k0*GG + g;
    const float* wLh = g_WLh + (size_t)k0*GG + g;
    const float* wLl = g_WLl + (size_t)k0*GG + g;

    for (int t = 0; t < NT; ++t){
        // ---- phase 1: attention-LSTM gates (split-k, 512 threads) ----
        {
            u64 a0, a1, a2, a3;
            if (hf == 0){
                const float* xp = g_xproj + ((size_t)t*BNUM + row0)*GG + g;
                a0 = pack2(xp[0],    xp[GG]);
                a1 = pack2(xp[2*GG], xp[3*GG]);
                a2 = pack2(xp[4*GG], xp[5*GG]);
                a3 = pack2(xp[6*GG], xp[7*GG]);
            } else { a0 = a1 = a2 = a3 = 0ull; }
            const float* hl = sm + R_HL + k0*8;
            const float* ha = sm + R_HA + k0*8;
            #pragma unroll 8
            for (int kk = 0; kk < 32; ++kk){
                u64 w0 = dup2(wAl[kk*GG]);
                u64 w1 = dup2(wAh[kk*GG]);
                ulonglong2 l0 = *(const ulonglong2*)(hl + kk*8);
                ulonglong2 l1 = *(const ulonglong2*)(hl + kk*8 + 4);
                ulonglong2 b0 = *(const ulonglong2*)(ha + kk*8);
                ulonglong2 b1 = *(const ulonglong2*)(ha + kk*8 + 4);
                fma2(a0, w0, l0.x); fma2(a0, w1, b0.x);
                fma2(a1, w0, l0.y); fma2(a1, w1, b0.y);
                fma2(a2, w0, l1.x); fma2(a2, w1, b1.x);
                fma2(a3, w0, l1.y); fma2(a3, w1, b1.y);
            }
            float* pp = sm + R_PART + hf*2048 + g;
            float2 f;
            f = unpack2(a0); pp[0]=f.x;    pp[256]=f.y;
            f = unpack2(a1); pp[512]=f.x;  pp[768]=f.y;
            f = unpack2(a2); pp[1024]=f.x; pp[1280]=f.y;
            f = unpack2(a3); pp[1536]=f.x; pp[1792]=f.y;
        }
        __syncthreads();
        // ---- phase 2: attention cell ----
        {
            const float* p = sm + R_PART + cr*256 + cu;
            float gi = p[0]   + p[2048];
            float gf = p[64]  + p[2112];
            float gg = p[128] + p[2176];
            float go = p[192] + p[2240];
            float c = sigf(gf)*sm[R_CA + cr*64 + cu] + sigf(gi)*tanhf(gg);
            sm[R_CA + cr*64 + cu] = c;
            sm[R_HA + cu*8 + cr]  = sigf(go)*tanhf(c);
        }
        __syncthreads();
        // ---- phase 3: hp[r][a][j] = h_att . w1[j][:64] ----
        {
            const float* hv = sm + R_HA + hr;
            const float* wv = sm + R_W1H + hav*2048 + hj;
            float acc = 0.f;
            #pragma unroll 8
            for (int k = 0; k < 64; ++k)
                acc += hv[k*8] * wv[k*32];
            sm[R_HP + (hr*2 + hav)*32 + hj] = acc;
        }
        __syncthreads();
        // ---- phase 4: scores ----
        if (tid < 400){
            const float* hp = sm + R_HP + (sr*2 + sa)*32;
            const float* pr = sm + R_PRE + sa*6400 + sr*25 + sn;
            const float* w2 = sm + R_W2A + sa*32;
            float acc = sm[R_B2A + sa];
            #pragma unroll 8
            for (int j = 0; j < 32; ++j)
                acc += fmaxf(hp[j] + pr[j*200], 0.f) * w2[j];
            sm[R_SS + (sr*2 + sa)*25 + sn] = acc;
        }
        __syncthreads();
        // ---- phase 5: softmax + weighted memory sum ----
        if (tid < 16){
            int r = tid >> 1, a = tid & 1;
            const float* sv  = sm + R_SS + (r*2 + a)*25;
            const float* mem = sm + R_MEM + a*800 + r*100;
            float m = sv[0];
            #pragma unroll
            for (int n = 1; n < 25; ++n) m = fmaxf(m, sv[n]);
            float s = 0.f, o0=0.f, o1=0.f, o2=0.f, o3=0.f;
            #pragma unroll
            for (int n = 0; n < 25; ++n){
                float e = __expf(sv[n]-m);
                s += e;
                o0 += e*mem[n*4+0]; o1 += e*mem[n*4+1];
                o2 += e*mem[n*4+2]; o3 += e*mem[n*4+3];
            }
            float inv = 1.0f/s;
            float* ao = sm + R_AO + r*8 + a*4;
            ao[0]=o0*inv; ao[1]=o1*inv; ao[2]=o2*inv; ao[3]=o3*inv;
        }
        __syncthreads();
        // ---- phase 6: trans layer 1 ----
        if (tid < 256){
            const float* ao = sm + R_AO + t1r*8;
            float acc = sm[R_TB1 + t1j];
            #pragma unroll
            for (int d = 0; d < 8; ++d)
                acc += ao[d] * sm[R_TW1T + d*32 + t1j];
            sm[R_T1 + t1r*32 + t1j] = fmaxf(acc, 0.f);
        }
        __syncthreads();
        // ---- phase 7: trans layer 2 ----
        {
            const float* t1v = sm + R_T1 + cr*32;
            const float* wv  = sm + R_TW2T + cu;
            float acc = sm[R_TB2 + cu];
            #pragma unroll 8
            for (int j = 0; j < 32; ++j)
                acc += t1v[j] * wv[j*64];
            sm[R_AV + cu*8 + cr] = acc;
        }
        __syncthreads();
        // ---- phase 8: language-LSTM gates (split-k) ----
        {
            u64 a0, a1, a2, a3;
            if (hf == 0){ u64 b = dup2(sm[R_BL + g]); a0=a1=a2=a3=b; }
            else { a0 = a1 = a2 = a3 = 0ull; }
            const float* av = sm + R_AV + k0*8;
            const float* hA = sm + R_HA + k0*8;
            const float* hL = sm + R_HL + k0*8;
            #pragma unroll 8
            for (int kk = 0; kk < 32; ++kk){
                u64 w0 = dup2(wLa[kk*GG]);
                u64 w1 = dup2(wLh[kk*GG]);
                u64 w2 = dup2(wLl[kk*GG]);
                ulonglong2 v0 = *(const ulonglong2*)(av + kk*8);
                ulonglong2 v1 = *(const ulonglong2*)(av + kk*8 + 4);
                ulonglong2 x0 = *(const ulonglong2*)(hA + kk*8);
                ulonglong2 x1 = *(const ulonglong2*)(hA + kk*8 + 4);
                ulonglong2 y0 = *(const ulonglong2*)(hL + kk*8);
                ulonglong2 y1 = *(const ulonglong2*)(hL + kk*8 + 4);
                fma2(a0, w0, v0.x); fma2(a0, w1, x0.x); fma2(a0, w2, y0.x);
                fma2(a1, w0, v0.y); fma2(a1, w1, x0.y); fma2(a1, w2, y0.y);
                fma2(a2, w0, v1.x); fma2(a2, w1, x1.x); fma2(a2, w2, y1.x);
                fma2(a3, w0, v1.y); fma2(a3, w1, x1.y); fma2(a3, w2, y1.y);
            }
            float* pp = sm + R_PART + hf*2048 + g;
            float2 f;
            f = unpack2(a0); pp[0]=f.x;    pp[256]=f.y;
            f = unpack2(a1); pp[512]=f.x;  pp[768]=f.y;
            f = unpack2(a2); pp[1024]=f.x; pp[1280]=f.y;
            f = unpack2(a3); pp[1536]=f.x; pp[1792]=f.y;
        }
        __syncthreads();
        // ---- phase 9: language cell + history write ----
        {
            const float* p = sm + R_PART + cr*256 + cu;
            float gi = p[0]   + p[2048];
            float gf = p[64]  + p[2112];
            float gg = p[128] + p[2176];
            float go = p[192] + p[2240];
            float c = sigf(gf)*sm[R_CL + cr*64 + cu] + sigf(gi)*tanhf(gg);
            sm[R_CL + cr*64 + cu] = c;
            float h = sigf(go)*tanhf(c);
            sm[R_HL + cu*8 + cr] = h;
            g_hist[((size_t)t*BNUM + row0 + cr)*RNNV + cu] = h;
        }
        __syncthreads();
    }
}

// ------------------------------------------------------------------
// fused output GEMM + log_softmax: CTA = 16 rows x 2001 cols, 512 threads
#define LST 18
__global__ __launch_bounds__(512) void output_kernel(const float* __restrict__ fcb,
                                                     float* __restrict__ out)
{
    extern __shared__ __align__(16) float s_logit[];   // [V1][LST]
    __shared__ __align__(16) float s_h[RNNV*16];        // [k][r]
    __shared__ float s_lse[16];
    const int tid = threadIdx.x;
    const int m0  = blockIdx.x * 16;

    {   // stage h history (transpose to [k][r]); 512 threads x 2 floats
        int i = tid * 2;
        int r = i >> 6, k = i & 63;
        float2 v = *(const float2*)(g_hist + (size_t)(m0 + r)*RNNV + k);
        s_h[k*16 + r]     = v.x;
        s_h[(k+1)*16 + r] = v.y;
    }
    __syncthreads();

    #pragma unroll
    for (int chunk = 0; chunk < 4; ++chunk){
        int c  = chunk*512 + tid;
        int cc = c < V1 ? c : V1-1;
        float bias = fcb[cc];
        u64 acc[8];
        #pragma unroll
        for (int p = 0; p < 8; ++p) acc[p] = dup2(bias);
        const float* w = g_fcwT + cc;
        #pragma unroll 8
        for (int k = 0; k < RNNV; ++k){
            u64 wd = dup2(w[(size_t)k*V1]);
            const float* hb = s_h + k*16;
            ulonglong2 h0 = *(const ulonglong2*)(hb);
            ulonglong2 h1 = *(const ulonglong2*)(hb + 4);
            ulonglong2 h2 = *(const ulonglong2*)(hb + 8);
            ulonglong2 h3 = *(const ulonglong2*)(hb + 12);
            fma2(acc[0], wd, h0.x); fma2(acc[1], wd, h0.y);
            fma2(acc[2], wd, h1.x); fma2(acc[3], wd, h1.y);
            fma2(acc[4], wd, h2.x); fma2(acc[5], wd, h2.y);
            fma2(acc[6], wd, h3.x); fma2(acc[7], wd, h3.y);
        }
        if (c < V1){
            #pragma unroll
            for (int p = 0; p < 8; ++p)
                *(u64*)(s_logit + c*LST + 2*p) = acc[p];
        }
    }
    __syncthreads();

    // per-row logsumexp: one warp per row
    {
        int r = tid >> 5, lane = tid & 31;
        float part = 0.0f;
        for (int c = lane; c < V1; c += 32)
            part += __expf(s_logit[c*LST + r]);
        #pragma unroll
        for (int o = 16; o; o >>= 1)
            part += __shfl_xor_sync(0xffffffffu, part, o);
        if (lane == 0) s_lse[r] = __logf(part);
    }
    __syncthreads();

    // write normalized log-probs: one warp per row, coalesced
    {
        int r = tid >> 5, lane = tid & 31;
        int m = m0 + r;
        int t = m >> 10, b = m & 1023;
        float lse = s_lse[r];
        float* dst = out + ((size_t)b*NT + t)*V1;
        for (int c = lane; c < V1; c += 32)
            dst[c] = s_logit[c*LST + r] - lse;
    }
}

// ------------------------------------------------------------------
extern "C" void kernel_launch(void* const* d_in, const int* in_sizes, int n_in,
                              void* d_out, int out_size)
{
    const int*   inst  = (const int*)  d_in[0];
    const float* prevc = (const float*)d_in[1];
    const float* finc  = (const float*)d_in[2];
    const float* embed = (const float*)d_in[3];
    const float* WihA  = (const float*)d_in[4];
    const float* WhhA  = (const float*)d_in[5];
    const float* bihA  = (const float*)d_in[6];
    const float* bhhA  = (const float*)d_in[7];
    const float* WihL  = (const float*)d_in[8];
    const float* WhhL  = (const float*)d_in[9];
    const float* bihL  = (const float*)d_in[10];
    const float* bhhL  = (const float*)d_in[11];
    const float* fcw   = (const float*)d_in[12];
    const float* fcb   = (const float*)d_in[13];
    const float* a1w1  = (const float*)d_in[14];
    const float* a1b1  = (const float*)d_in[15];
    const float* a1w2  = (const float*)d_in[16];
    const float* a1b2  = (const float*)d_in[17];
    const float* a2w1  = (const float*)d_in[18];
    const float* a2b1  = (const float*)d_in[19];
    const float* a2w2  = (const float*)d_in[20];
    const float* a2b2  = (const float*)d_in[21];
    const float* tw1   = (const float*)d_in[22];
    const float* tb1   = (const float*)d_in[23];
    const float* tw2   = (const float*)d_in[24];
    const float* tb2   = (const float*)d_in[25];
    float* out = (float*)d_out;

    static int smem_set = 0;
    const int logit_smem = V1 * LST * (int)sizeof(float);
    const int rec_smem   = R_TOTAL * (int)sizeof(float);
    if (!smem_set){
        cudaFuncSetAttribute(output_kernel,    cudaFuncAttributeMaxDynamicSharedMemorySize, logit_smem);
        cudaFuncSetAttribute(recurrent_kernel, cudaFuncAttributeMaxDynamicSharedMemorySize, rec_smem);
        smem_set = 1;
    }

    prep_weights_kernel<<<(RNNV*V1 + 255)/256, 256>>>(WihA, WhhA, WihL, WhhL, fcw);
    prep_canvas_kernel<<<(BNUM*NOBJ*HID + 255)/256, 256>>>(prevc, finc, a1w1, a1b1, a2w1, a2b1);
    xproj_kernel<<<NROW/16, 256>>>(inst, embed, bihA, bhhA);
    recurrent_kernel<<<BNUM/8, 512, rec_smem>>>(a1w1, a1w2, a1b2, a2w1, a2w2, a2b2,
                                                tw1, tb1, tw2, tb2, bihL, bhhL, prevc);
    output_kernel<<<NROW/16, 512, logit_smem>>>(fcb, out);
}

// round 4
// speedup vs baseline: 1.5176x; 1.1786x over previous
#include <cuda_runtime.h>
#include <math.h>

#define BNUM 1024
#define TT   48
#define NT   47
#define RNNV 64
#define GG   256
#define NOBJ 25
#define HID  32
#define V1   2001
#define V1P  2002
#define NROW (NT*BNUM)

__device__ float g_xproj[(size_t)NROW*GG];
__device__ float g_hist[(size_t)NROW*RNNV];
__device__ float g_pre1[BNUM*NOBJ*HID];
__device__ float g_pre2[BNUM*NOBJ*HID];
__device__ float g_diff[BNUM*NOBJ*4];
__device__ float g_WAl[RNNV*GG], g_WAh[RNNV*GG], g_WAx[RNNV*GG];
__device__ float g_WLa[RNNV*GG], g_WLh[RNNV*GG], g_WLl[RNNV*GG];
__device__ float g_fcwT[RNNV*V1P + 4];

typedef unsigned long long u64;

__device__ __forceinline__ u64 pack2(float lo, float hi){
    u64 r; asm("mov.b64 %0, {%1, %2};" : "=l"(r) : "f"(lo), "f"(hi)); return r;
}
__device__ __forceinline__ u64 dup2(float x){ return pack2(x, x); }
__device__ __forceinline__ void fma2(u64& acc, u64 a, u64 b){
    asm("fma.rn.f32x2 %0, %1, %2, %0;" : "+l"(acc) : "l"(a), "l"(b));
}
__device__ __forceinline__ float2 unpack2(u64 v){
    float2 f; asm("mov.b64 {%0, %1}, %2;" : "=f"(f.x), "=f"(f.y) : "l"(v)); return f;
}
__device__ __forceinline__ float sigf(float x){
    return __fdividef(1.0f, 1.0f + __expf(-x));
}
__device__ __forceinline__ float ftanh(float x){
    float e = __expf(-2.0f*x);
    return __fdividef(1.0f - e, 1.0f + e);
}

// ------------------------------------------------------------------
__global__ void prep_weights_kernel(const float* __restrict__ WihA, const float* __restrict__ WhhA,
                                    const float* __restrict__ WihL, const float* __restrict__ WhhL,
                                    const float* __restrict__ fcw)
{
    int i = blockIdx.x*blockDim.x + threadIdx.x;
    if (i < RNNV*GG){
        int k = i / GG, g = i % GG;
        g_WAl[i] = WihA[g*128 + k];
        g_WAx[i] = WihA[g*128 + 64 + k];
        g_WAh[i] = WhhA[g*64 + k];
        g_WLa[i] = WihL[g*128 + k];
        g_WLh[i] = WihL[g*128 + 64 + k];
        g_WLl[i] = WhhL[g*64 + k];
    }
    if (i < RNNV*V1){
        int k = i / V1, v = i % V1;
        g_fcwT[k*V1P + v] = fcw[v*RNNV + k];
    }
}

// ------------------------------------------------------------------
__global__ void prep_canvas_kernel(const float* __restrict__ prev, const float* __restrict__ finalc,
                                   const float* __restrict__ a1w1, const float* __restrict__ a1b1,
                                   const float* __restrict__ a2w1, const float* __restrict__ a2b1)
{
    int i = blockIdx.x*blockDim.x + threadIdx.x;
    if (i >= BNUM*NOBJ*HID) return;
    int j = i & 31, bn = i >> 5;
    float p0 = prev[bn*4+0], p1 = prev[bn*4+1], p2 = prev[bn*4+2], p3 = prev[bn*4+3];
    bool masked = (p0+p1+p2+p3) > 0.0f;
    float d0 = masked ? -1.0f : finalc[bn*4+0];
    float d1 = masked ? -1.0f : finalc[bn*4+1];
    float d2 = masked ? -1.0f : finalc[bn*4+2];
    float d3 = masked ? -1.0f : finalc[bn*4+3];
    const float* w1 = a1w1 + j*68 + 64;
    const float* w2 = a2w1 + j*68 + 64;
    g_pre1[i] = a1b1[j] + d0*w1[0] + d1*w1[1] + d2*w1[2] + d3*w1[3];
    g_pre2[i] = a2b1[j] + p0*w2[0] + p1*w2[1] + p2*w2[2] + p3*w2[3];
    if (j == 0){
        g_diff[bn*4+0] = d0; g_diff[bn*4+1] = d1;
        g_diff[bn*4+2] = d2; g_diff[bn*4+3] = d3;
    }
}

// ------------------------------------------------------------------
__global__ __launch_bounds__(256) void xproj_kernel(
    const int* __restrict__ inst, const float* __restrict__ embed,
    const float* __restrict__ b_ih, const float* __restrict__ b_hh)
{
    __shared__ __align__(16) float se[RNNV*16];  // [k][r]
    const int tid = threadIdx.x;
    const int m0 = blockIdx.x * 16;
    for (int i = tid; i < 16*RNNV; i += 256){
        int r = i >> 6, k = i & 63;
        int m = m0 + r;
        int t = m >> 10, b = m & 1023;
        int tok = inst[b*TT + t];
        se[k*16 + r] = embed[tok*RNNV + k];
    }
    __syncthreads();
    const int g = tid;
    float bias = b_ih[g] + b_hh[g];
    u64 acc[8];
    #pragma unroll
    for (int p = 0; p < 8; ++p) acc[p] = dup2(bias);
    const float* w = g_WAx + g;
    #pragma unroll 8
    for (int k = 0; k < RNNV; ++k){
        u64 wd = dup2(w[k*GG]);
        const float* e = se + k*16;
        ulonglong2 e0 = *(const ulonglong2*)(e);
        ulonglong2 e1 = *(const ulonglong2*)(e + 4);
        ulonglong2 e2 = *(const ulonglong2*)(e + 8);
        ulonglong2 e3 = *(const ulonglong2*)(e + 12);
        fma2(acc[0], wd, e0.x); fma2(acc[1], wd, e0.y);
        fma2(acc[2], wd, e1.x); fma2(acc[3], wd, e1.y);
        fma2(acc[4], wd, e2.x); fma2(acc[5], wd, e2.y);
        fma2(acc[6], wd, e3.x); fma2(acc[7], wd, e3.y);
    }
    float* xp = g_xproj + (size_t)m0*GG + g;
    #pragma unroll
    for (int p = 0; p < 8; ++p){
        float2 f = unpack2(acc[p]);
        xp[(size_t)(2*p)*GG]   = f.x;
        xp[(size_t)(2*p+1)*GG] = f.y;
    }
}

// ------------------------------------------------------------------
// recurrent smem layout (float offsets)
#define R_HL    0        // 512  [k][8]
#define R_HA    512      // 512  [k][8]
#define R_AV    1024     // 512  [k][8]
#define R_HAR   1536     // 512  [r][64]
#define R_CA    2048     // 512  [r][u]
#define R_CL    2560     // 512
#define R_PART  3072     // 4096 [hf][r][g]
#define R_PRE   7168     // 14400 [a][r][n*36+j]
#define R_W1H   21568    // 4352  [a][j*68+k]
#define R_TW2T  25920    // 2304  [u*36+j]
#define R_MEM   28224    // 1600  [a][r][n*4+d]
#define R_HP    29824    // 512   [r][a*32+j]
#define R_AO    30336    // 64    [r][8]
#define R_T1    30400    // 256   [r][j]
#define R_TW1T  30656    // 256   [d][j]
#define R_W2A   30912    // 64    [a][j]
#define R_TB1   30976    // 32
#define R_TB2   31008    // 64
#define R_BL    31072    // 256
#define R_B2A   31328    // 2
#define R_TOTAL 31336

__global__ __launch_bounds__(512) void recurrent_kernel(
    const float* __restrict__ a1w1, const float* __restrict__ a1w2, const float* __restrict__ a1b2,
    const float* __restrict__ a2w1, const float* __restrict__ a2w2, const float* __restrict__ a2b2,
    const float* __restrict__ tw1,  const float* __restrict__ tb1,
    const float* __restrict__ tw2,  const float* __restrict__ tb2,
    const float* __restrict__ bihl, const float* __restrict__ bhhl,
    const float* __restrict__ prev)
{
    extern __shared__ __align__(16) float sm[];
    const int tid  = threadIdx.x;
    const int row0 = blockIdx.x * 8;

    // ------- one-time init -------
    for (int i = tid; i < 3072; i += 512) sm[i] = 0.f;   // HL HA AV HAR CA CL
    for (int i = tid; i < 12800; i += 512){
        int a = i / 6400, rem = i % 6400;
        int r = rem / 800, rem2 = rem % 800;
        int n = rem2 >> 5, j = rem2 & 31;
        const float* src = a ? g_pre2 : g_pre1;
        sm[R_PRE + a*7200 + r*900 + n*36 + j] = src[((size_t)(row0+r)*NOBJ + n)*HID + j];
    }
    for (int i = tid; i < 4096; i += 512){
        int a = i >> 11, j = (i >> 6) & 31, k = i & 63;
        sm[R_W1H + a*2176 + j*68 + k] = (a ? a2w1 : a1w1)[j*68 + k];
    }
    for (int i = tid; i < 2048; i += 512){
        int u = i >> 5, j = i & 31;
        sm[R_TW2T + u*36 + j] = tw2[u*HID + j];
    }
    for (int i = tid; i < 1600; i += 512){
        int a = i / 800, rem = i % 800, r = rem / 100, q = rem % 100;
        sm[R_MEM + i] = a ? prev[(row0+r)*100 + q] : g_diff[(row0+r)*100 + q];
    }
    if (tid < 256){ int j = tid >> 3, d = tid & 7; sm[R_TW1T + d*32 + j] = tw1[j*8 + d]; }
    if (tid < 32){
        sm[R_W2A + tid]      = a1w2[tid];
        sm[R_W2A + 32 + tid] = a2w2[tid];
        sm[R_TB1 + tid]      = tb1[tid];
    }
    if (tid < 64)  sm[R_TB2 + tid] = tb2[tid];
    if (tid < 256) sm[R_BL + tid]  = bihl[tid] + bhhl[tid];
    if (tid < 2)   sm[R_B2A + tid] = tid ? a2b2[0] : a1b2[0];
    __syncthreads();

    // ------- hoisted per-thread indices -------
    const int g    = tid & 255;
    const int hf   = tid >> 8;
    const int k0   = hf << 5;
    const int wid  = tid >> 5;
    const int lane = tid & 31;
    const int cu   = tid & 63, cr = tid >> 6;

    const float* wAl = g_WAl + (size_t)k0*GG + g;
    const float* wAh = g_WAh + (size_t)k0*GG + g;
    const float* wLa = g_WLa + (size_t)k0*GG + g;
    const float* wLh = g_WLh + (size_t)k0*GG + g;
    const float* wLl = g_WLl + (size_t)k0*GG + g;

    for (int t = 0; t < NT; ++t){
        // ==== phase 1: attention-LSTM gates (split-k, 512 threads) ====
        {
            float x0=0,x1=0,x2=0,x3=0,x4=0,x5=0,x6=0,x7=0;
            if (hf == 0){
                const float* xp = g_xproj + ((size_t)t*BNUM + row0)*GG + g;
                x0=xp[0];    x1=xp[GG];   x2=xp[2*GG]; x3=xp[3*GG];
                x4=xp[4*GG]; x5=xp[5*GG]; x6=xp[6*GG]; x7=xp[7*GG];
            }
            u64 a0=0, a1=0, a2=0, a3=0;
            const float* hl = sm + R_HL + k0*8;
            const float* ha = sm + R_HA + k0*8;
            #pragma unroll 8
            for (int kk = 0; kk < 32; ++kk){
                u64 w0 = dup2(wAl[kk*GG]);
                u64 w1 = dup2(wAh[kk*GG]);
                ulonglong2 l0 = *(const ulonglong2*)(hl + kk*8);
                ulonglong2 l1 = *(const ulonglong2*)(hl + kk*8 + 4);
                ulonglong2 b0 = *(const ulonglong2*)(ha + kk*8);
                ulonglong2 b1 = *(const ulonglong2*)(ha + kk*8 + 4);
                fma2(a0, w0, l0.x); fma2(a0, w1, b0.x);
                fma2(a1, w0, l0.y); fma2(a1, w1, b0.y);
                fma2(a2, w0, l1.x); fma2(a2, w1, b1.x);
                fma2(a3, w0, l1.y); fma2(a3, w1, b1.y);
            }
            float* pp = sm + R_PART + hf*2048 + g;
            float2 f;
            f = unpack2(a0); pp[0]=f.x+x0;    pp[256]=f.y+x1;
            f = unpack2(a1); pp[512]=f.x+x2;  pp[768]=f.y+x3;
            f = unpack2(a2); pp[1024]=f.x+x4; pp[1280]=f.y+x5;
            f = unpack2(a3); pp[1536]=f.x+x6; pp[1792]=f.y+x7;
        }
        __syncthreads();
        // ==== phase [2+3]: attention cell + hp, warp-per-row ====
        if (wid < 8){
            const int r = wid;
            #pragma unroll
            for (int h = 0; h < 2; ++h){
                int u = lane + h*32;
                const float* p = sm + R_PART + r*256 + u;
                float gi = p[0]   + p[2048];
                float gf = p[64]  + p[2112];
                float gg = p[128] + p[2176];
                float go = p[192] + p[2240];
                float c = sigf(gf)*sm[R_CA + r*64 + u] + sigf(gi)*ftanh(gg);
                sm[R_CA + r*64 + u] = c;
                float hv = sigf(go)*ftanh(c);
                sm[R_HA + u*8 + r]  = hv;
                sm[R_HAR + r*64 + u] = hv;
            }
            __syncwarp();
            const float4* hv4 = (const float4*)(sm + R_HAR + r*64);
            const float4* w0v = (const float4*)(sm + R_W1H + lane*68);
            const float4* w1v = (const float4*)(sm + R_W1H + 2176 + lane*68);
            float acc0 = 0.f, acc1 = 0.f;
            #pragma unroll
            for (int q = 0; q < 16; ++q){
                float4 h4 = hv4[q], wa = w0v[q], wb = w1v[q];
                acc0 += h4.x*wa.x + h4.y*wa.y + h4.z*wa.z + h4.w*wa.w;
                acc1 += h4.x*wb.x + h4.y*wb.y + h4.z*wb.z + h4.w*wb.w;
            }
            sm[R_HP + r*64 + lane]      = acc0;
            sm[R_HP + r*64 + 32 + lane] = acc1;
        }
        __syncthreads();
        // ==== phase [4+5]: scores + softmax + weighted sum, warp-per-(r,a) ====
        {
            const int r = wid >> 1, a = wid & 1;
            float sc = -1e30f;
            if (lane < 25){
                const float4* hp = (const float4*)(sm + R_HP + r*64 + a*32);
                const float4* pr = (const float4*)(sm + R_PRE + a*7200 + r*900 + lane*36);
                const float4* w2 = (const float4*)(sm + R_W2A + a*32);
                float acc = sm[R_B2A + a];
                #pragma unroll
                for (int q = 0; q < 8; ++q){
                    float4 h4 = hp[q], p4 = pr[q], w4 = w2[q];
                    acc += fmaxf(h4.x+p4.x, 0.f)*w4.x + fmaxf(h4.y+p4.y, 0.f)*w4.y
                         + fmaxf(h4.z+p4.z, 0.f)*w4.z + fmaxf(h4.w+p4.w, 0.f)*w4.w;
                }
                sc = acc;
            }
            float m = sc;
            #pragma unroll
            for (int o = 16; o; o >>= 1) m = fmaxf(m, __shfl_xor_sync(0xffffffffu, m, o));
            float e = 0.f, o0=0.f, o1=0.f, o2=0.f, o3=0.f;
            if (lane < 25){
                e = __expf(sc - m);
                float4 mv = *(const float4*)(sm + R_MEM + a*800 + r*100 + lane*4);
                o0 = e*mv.x; o1 = e*mv.y; o2 = e*mv.z; o3 = e*mv.w;
            }
            float s = e;
            #pragma unroll
            for (int o = 16; o; o >>= 1){
                s  += __shfl_xor_sync(0xffffffffu, s,  o);
                o0 += __shfl_xor_sync(0xffffffffu, o0, o);
                o1 += __shfl_xor_sync(0xffffffffu, o1, o);
                o2 += __shfl_xor_sync(0xffffffffu, o2, o);
                o3 += __shfl_xor_sync(0xffffffffu, o3, o);
            }
            if (lane == 0){
                float inv = __fdividef(1.0f, s);
                float* ao = sm + R_AO + r*8 + a*4;
                ao[0]=o0*inv; ao[1]=o1*inv; ao[2]=o2*inv; ao[3]=o3*inv;
            }
        }
        __syncthreads();
        // ==== phase [6+7]: trans MLP, warp-per-row ====
        if (wid < 8){
            const int r = wid, j = lane;
            const float* ao = sm + R_AO + r*8;
            float acc = sm[R_TB1 + j];
            #pragma unroll
            for (int d = 0; d < 8; ++d)
                acc += ao[d] * sm[R_TW1T + d*32 + j];
            sm[R_T1 + r*32 + j] = fmaxf(acc, 0.f);
            __syncwarp();
            const float4* t1v = (const float4*)(sm + R_T1 + r*32);
            const float4* wv0 = (const float4*)(sm + R_TW2T + lane*36);
            const float4* wv1 = (const float4*)(sm + R_TW2T + (lane+32)*36);
            float b0 = sm[R_TB2 + lane], b1 = sm[R_TB2 + lane + 32];
            #pragma unroll
            for (int q = 0; q < 8; ++q){
                float4 t4 = t1v[q], wa = wv0[q], wb = wv1[q];
                b0 += t4.x*wa.x + t4.y*wa.y + t4.z*wa.z + t4.w*wa.w;
                b1 += t4.x*wb.x + t4.y*wb.y + t4.z*wb.z + t4.w*wb.w;
            }
            sm[R_AV + lane*8 + r]      = b0;
            sm[R_AV + (lane+32)*8 + r] = b1;
        }
        __syncthreads();
        // ==== phase 8: language-LSTM gates (split-k) ====
        {
            u64 a0, a1, a2, a3;
            if (hf == 0){ u64 b = dup2(sm[R_BL + g]); a0=a1=a2=a3=b; }
            else { a0 = a1 = a2 = a3 = 0ull; }
            const float* av = sm + R_AV + k0*8;
            const float* hA = sm + R_HA + k0*8;
            const float* hL = sm + R_HL + k0*8;
            #pragma unroll 8
            for (int kk = 0; kk < 32; ++kk){
                u64 w0 = dup2(wLa[kk*GG]);
                u64 w1 = dup2(wLh[kk*GG]);
                u64 w2 = dup2(wLl[kk*GG]);
                ulonglong2 v0 = *(const ulonglong2*)(av + kk*8);
                ulonglong2 v1 = *(const ulonglong2*)(av + kk*8 + 4);
                ulonglong2 x0 = *(const ulonglong2*)(hA + kk*8);
                ulonglong2 x1 = *(const ulonglong2*)(hA + kk*8 + 4);
                ulonglong2 y0 = *(const ulonglong2*)(hL + kk*8);
                ulonglong2 y1 = *(const ulonglong2*)(hL + kk*8 + 4);
                fma2(a0, w0, v0.x); fma2(a0, w1, x0.x); fma2(a0, w2, y0.x);
                fma2(a1, w0, v0.y); fma2(a1, w1, x0.y); fma2(a1, w2, y0.y);
                fma2(a2, w0, v1.x); fma2(a2, w1, x1.x); fma2(a2, w2, y1.x);
                fma2(a3, w0, v1.y); fma2(a3, w1, x1.y); fma2(a3, w2, y1.y);
            }
            float* pp = sm + R_PART + hf*2048 + g;
            float2 f;
            f = unpack2(a0); pp[0]=f.x;    pp[256]=f.y;
            f = unpack2(a1); pp[512]=f.x;  pp[768]=f.y;
            f = unpack2(a2); pp[1024]=f.x; pp[1280]=f.y;
            f = unpack2(a3); pp[1536]=f.x; pp[1792]=f.y;
        }
        __syncthreads();
        // ==== phase 9: language cell + history ====
        {
            const float* p = sm + R_PART + cr*256 + cu;
            float gi = p[0]   + p[2048];
            float gf = p[64]  + p[2112];
            float gg = p[128] + p[2176];
            float go = p[192] + p[2240];
            float c = sigf(gf)*sm[R_CL + cr*64 + cu] + sigf(gi)*ftanh(gg);
            sm[R_CL + cr*64 + cu] = c;
            float h = sigf(go)*ftanh(c);
            sm[R_HL + cu*8 + cr] = h;
            g_hist[((size_t)t*BNUM + row0 + cr)*RNNV + cu] = h;
        }
        __syncthreads();
    }
}

// ------------------------------------------------------------------
// fused output GEMM + log_softmax: 16 rows x 2001 cols, row-major smem logits
#define OST 2004
__global__ __launch_bounds__(512) void output_kernel(const float* __restrict__ fcb,
                                                     float* __restrict__ out)
{
    extern __shared__ __align__(16) float s_logit[];   // [16][OST]
    __shared__ __align__(16) float s_h[RNNV*16];        // [k][r]
    const int tid = threadIdx.x;
    const int m0  = blockIdx.x * 16;

    {   // stage h history (transpose to [k][r])
        int i = tid * 2;
        int r = i >> 6, k = i & 63;
        float2 v = *(const float2*)(g_hist + (size_t)(m0 + r)*RNNV + k);
        s_h[k*16 + r]     = v.x;
        s_h[(k+1)*16 + r] = v.y;
    }
    if (tid < 48){   // guard cols 2001..2003
        int r = tid / 3, c = V1 + tid % 3;
        s_logit[r*OST + c] = -1e30f;
    }
    __syncthreads();

    #pragma unroll
    for (int chunk = 0; chunk < 2; ++chunk){
        int c0 = chunk*1024 + tid*2;
        float bx = (c0   < V1) ? fcb[c0]   : 0.f;
        float by = (c0+1 < V1) ? fcb[c0+1] : 0.f;
        u64 acc[16];
        u64 binit = pack2(bx, by);
        #pragma unroll
        for (int r = 0; r < 16; ++r) acc[r] = binit;
        const float* w = g_fcwT + c0;
        #pragma unroll 4
        for (int k = 0; k < RNNV; ++k){
            u64 wv = *(const u64*)(w + (size_t)k*V1P);
            const float* hb = s_h + k*16;
            float4 h0 = *(const float4*)(hb);
            float4 h1 = *(const float4*)(hb + 4);
            float4 h2 = *(const float4*)(hb + 8);
            float4 h3 = *(const float4*)(hb + 12);
            fma2(acc[0],  wv, dup2(h0.x)); fma2(acc[1],  wv, dup2(h0.y));
            fma2(acc[2],  wv, dup2(h0.z)); fma2(acc[3],  wv, dup2(h0.w));
            fma2(acc[4],  wv, dup2(h1.x)); fma2(acc[5],  wv, dup2(h1.y));
            fma2(acc[6],  wv, dup2(h1.z)); fma2(acc[7],  wv, dup2(h1.w));
            fma2(acc[8],  wv, dup2(h2.x)); fma2(acc[9],  wv, dup2(h2.y));
            fma2(acc[10], wv, dup2(h2.z)); fma2(acc[11], wv, dup2(h2.w));
            fma2(acc[12], wv, dup2(h3.x)); fma2(acc[13], wv, dup2(h3.y));
            fma2(acc[14], wv, dup2(h3.z)); fma2(acc[15], wv, dup2(h3.w));
        }
        if (c0 + 1 < V1){
            #pragma unroll
            for (int r = 0; r < 16; ++r)
                *(u64*)(s_logit + r*OST + c0) = acc[r];
        } else if (c0 < V1){
            #pragma unroll
            for (int r = 0; r < 16; ++r){
                float2 f = unpack2(acc[r]);
                s_logit[r*OST + c0] = f.x;
            }
        }
    }
    __syncthreads();

    // warp-per-row: logsumexp (register reduce) + write
    {
        const int r = tid >> 5, lane = tid & 31;
        const float4* row = (const float4*)(s_logit + r*OST);
        float s = 0.f;
        for (int q = lane; q < 501; q += 32){
            float4 f = row[q];
            s += __expf(f.x) + __expf(f.y) + __expf(f.z) + __expf(f.w);
        }
        #pragma unroll
        for (int o = 16; o; o >>= 1)
            s += __shfl_xor_sync(0xffffffffu, s, o);
        float lse = __logf(s);

        int m = m0 + r;
        int t = m >> 10, b = m & 1023;
        float* dst = out + ((size_t)b*NT + t)*V1;
        for (int q = lane; q < 501; q += 32){
            float4 f = row[q];
            int c = q*4;
            if (c + 3 < V1){
                dst[c]   = f.x - lse;
                dst[c+1] = f.y - lse;
                dst[c+2] = f.z - lse;
                dst[c+3] = f.w - lse;
            } else {
                if (c   < V1) dst[c]   = f.x - lse;
                if (c+1 < V1) dst[c+1] = f.y - lse;
                if (c+2 < V1) dst[c+2] = f.z - lse;
            }
        }
    }
}

// ------------------------------------------------------------------
extern "C" void kernel_launch(void* const* d_in, const int* in_sizes, int n_in,
                              void* d_out, int out_size)
{
    const int*   inst  = (const int*)  d_in[0];
    const float* prevc = (const float*)d_in[1];
    const float* finc  = (const float*)d_in[2];
    const float* embed = (const float*)d_in[3];
    const float* WihA  = (const float*)d_in[4];
    const float* WhhA  = (const float*)d_in[5];
    const float* bihA  = (const float*)d_in[6];
    const float* bhhA  = (const float*)d_in[7];
    const float* WihL  = (const float*)d_in[8];
    const float* WhhL  = (const float*)d_in[9];
    const float* bihL  = (const float*)d_in[10];
    const float* bhhL  = (const float*)d_in[11];
    const float* fcw   = (const float*)d_in[12];
    const float* fcb   = (const float*)d_in[13];
    const float* a1w1  = (const float*)d_in[14];
    const float* a1b1  = (const float*)d_in[15];
    const float* a1w2  = (const float*)d_in[16];
    const float* a1b2  = (const float*)d_in[17];
    const float* a2w1  = (const float*)d_in[18];
    const float* a2b1  = (const float*)d_in[19];
    const float* a2w2  = (const float*)d_in[20];
    const float* a2b2  = (const float*)d_in[21];
    const float* tw1   = (const float*)d_in[22];
    const float* tb1   = (const float*)d_in[23];
    const float* tw2   = (const float*)d_in[24];
    const float* tb2   = (const float*)d_in[25];
    float* out = (float*)d_out;

    static int smem_set = 0;
    const int logit_smem = 16 * OST * (int)sizeof(float);
    const int rec_smem   = R_TOTAL * (int)sizeof(float);
    if (!smem_set){
        cudaFuncSetAttribute(output_kernel,    cudaFuncAttributeMaxDynamicSharedMemorySize, logit_smem);
        cudaFuncSetAttribute(recurrent_kernel, cudaFuncAttributeMaxDynamicSharedMemorySize, rec_smem);
        smem_set = 1;
    }

    prep_weights_kernel<<<(RNNV*V1 + 255)/256, 256>>>(WihA, WhhA, WihL, WhhL, fcw);
    prep_canvas_kernel<<<(BNUM*NOBJ*HID + 255)/256, 256>>>(prevc, finc, a1w1, a1b1, a2w1, a2b1);
    xproj_kernel<<<NROW/16, 256>>>(inst, embed, bihA, bhhA);
    recurrent_kernel<<<BNUM/8, 512, rec_smem>>>(a1w1, a1w2, a1b2, a2w1, a2w2, a2b2,
                                                tw1, tb1, tw2, tb2, bihL, bhhL, prevc);
    output_kernel<<<NROW/16, 512, logit_smem>>>(fcb, out);
}